// round 4
// baseline (speedup 1.0000x reference)
#include <cuda_runtime.h>
#include <cstdint>
#include <cstddef>

// Problem constants
#define BB    64
#define VV    32000
#define EE    512
#define HH    1024
#define G3    3072
#define TT    64
#define DINIT 768
#define DATT  256

// ---------------- scratch (device globals; no allocations allowed) ----------
__device__ float g_h[BB * HH];                 // hidden state (in-place update)
__device__ float g_gi[BB * G3];                // x @ W_ih^T + b_ih
__device__ float g_gh[BB * G3];                // h @ W_hh^T + b_hh
__device__ unsigned long long g_slots[BB];     // packed argmax slots

// ---------------- f32x2 packed math helpers ---------------------------------
__device__ __forceinline__ unsigned long long pack2(float lo, float hi) {
    unsigned long long r;
    asm("mov.b64 %0, {%1,%2};" : "=l"(r) : "f"(lo), "f"(hi));
    return r;
}
__device__ __forceinline__ unsigned long long fma2(unsigned long long a,
                                                   unsigned long long b,
                                                   unsigned long long c) {
    unsigned long long d;
    asm("fma.rn.f32x2 %0, %1, %2, %3;" : "=l"(d) : "l"(a), "l"(b), "l"(c));
    return d;
}
__device__ __forceinline__ float2 unpack2(unsigned long long v) {
    float2 f;
    asm("mov.b64 {%0,%1}, %2;" : "=f"(f.x), "=f"(f.y) : "l"(v));
    return f;
}

// ---------------- threefry2x32 (exact JAX schedule) --------------------------
__host__ __device__ static inline void tf2x32(unsigned k0, unsigned k1,
                                              unsigned x0, unsigned x1,
                                              unsigned* o0, unsigned* o1) {
    unsigned ks2 = k0 ^ k1 ^ 0x1BD11BDAu;
#define TF_RND(R) { x0 += x1; x1 = (x1 << (R)) | (x1 >> (32 - (R))); x1 ^= x0; }
    x0 += k0; x1 += k1;
    TF_RND(13) TF_RND(15) TF_RND(26) TF_RND(6)
    x0 += k1;  x1 += ks2 + 1u;
    TF_RND(17) TF_RND(29) TF_RND(16) TF_RND(24)
    x0 += ks2; x1 += k0 + 2u;
    TF_RND(13) TF_RND(15) TF_RND(26) TF_RND(6)
    x0 += k0;  x1 += k1 + 3u;
    TF_RND(17) TF_RND(29) TF_RND(16) TF_RND(24)
    x0 += k1;  x1 += ks2 + 4u;
    TF_RND(13) TF_RND(15) TF_RND(26) TF_RND(6)
    x0 += ks2; x1 += k0 + 5u;
#undef TF_RND
    *o0 = x0; *o1 = x1;
}

// JAX partitionable random_bits (32-bit): counter = 64-bit flat index e
// (hi = 0 for our sizes), draw = o0 ^ o1.
__device__ __forceinline__ unsigned jax_bits32(unsigned k0, unsigned k1,
                                               unsigned e) {
    unsigned o0, o1;
    tf2x32(k0, k1, 0u, e, &o0, &o1);
    return o0 ^ o1;
}

// JAX uniform->gumbel:  u0 = bitcast((bits>>9)|0x3f800000)-1 ; u = max(tiny, u0)
// gumbel = -log(-log(u))
__device__ __forceinline__ float gumbel_from_bits(unsigned bits) {
    float u = __uint_as_float((bits >> 9) | 0x3f800000u) - 1.0f;
    u = u + 1.17549435082228750797e-38f;   // == max(tiny, u0) in fp32
    return -logf(-logf(u));
}

__device__ __forceinline__ unsigned orderf(float f) {
    unsigned u = __float_as_uint(f);
    return (u & 0x80000000u) ? ~u : (u | 0x80000000u);
}

__device__ __forceinline__ int decode_sid(unsigned long long slot) {
    return (int)(0xFFFFFFFFu - (unsigned)(slot & 0xFFFFFFFFull));
}

// ---------------- init: h0 = concat(init_hidden, att_embedding) --------------
__global__ void init_kernel(const float* __restrict__ init_hidden,
                            const float* __restrict__ att) {
    int i = blockIdx.x * blockDim.x + threadIdx.x;   // [0, B*H)
    int b = i / HH, u = i % HH;
    g_h[i] = (u < DINIT) ? init_hidden[b * DINIT + u]
                         : att[b * DATT + (u - DINIT)];
}

// ---------------- generic 64xN tile SGEMM (f32x2), used for gates + logits ---
// phase 0: blocks [0,48)   -> gi = X(gathered emb rows) @ W_ih^T + b_ih
//          blocks [48,96)  -> gh = h @ W_hh^T + b_hh
// phase 1: blocks [0,500)  -> logits tile, C = out (already offset to step t)
__global__ __launch_bounds__(256) void sgemm_step(
    const float* __restrict__ emb,
    const int*   __restrict__ inputs,
    const float* __restrict__ Wih, const float* __restrict__ Whh,
    const float* __restrict__ bih, const float* __restrict__ bhh,
    const float* __restrict__ Wout, const float* __restrict__ bout,
    float* __restrict__ out, int t, int phase) {

    __shared__ __align__(16) float As[16][64];
    __shared__ __align__(16) float Bs[16][64];
    __shared__ const float* rowp[64];

    const float* W; const float* bias; float* C;
    int K, ldc, ncol0;
    bool gather = false;
    if (phase == 0) {
        if (blockIdx.x < 48) {
            gather = true; W = Wih; bias = bih; C = g_gi;
            K = EE; ldc = G3; ncol0 = blockIdx.x * 64;
        } else {
            W = Whh; bias = bhh; C = g_gh;
            K = HH; ldc = G3; ncol0 = (blockIdx.x - 48) * 64;
        }
    } else {
        W = Wout; bias = bout; C = out;
        K = HH; ldc = VV; ncol0 = blockIdx.x * 64;
    }

    const int tid = threadIdx.x;
    if (tid < 64) {
        if (gather) {
            int sid = (t == 0) ? inputs[tid] : decode_sid(g_slots[tid]);
            rowp[tid] = emb + (size_t)sid * EE;
        } else {
            rowp[tid] = g_h + (size_t)tid * HH;
        }
    }
    __syncthreads();

    const int lm = tid >> 2;          // row loaded by this thread (0..63)
    const int lk = (tid & 3) << 2;    // k offset (0,4,8,12)

    // first tile
    {
        float4 a  = *(const float4*)(rowp[lm] + lk);
        float4 bt = *(const float4*)(W + (size_t)(ncol0 + lm) * K + lk);
        As[lk + 0][lm] = a.x;  As[lk + 1][lm] = a.y;
        As[lk + 2][lm] = a.z;  As[lk + 3][lm] = a.w;
        Bs[lk + 0][lm] = bt.x; Bs[lk + 1][lm] = bt.y;
        Bs[lk + 2][lm] = bt.z; Bs[lk + 3][lm] = bt.w;
    }
    __syncthreads();

    const int tx = tid & 15;   // n-group: cols ncol0 + tx*4 .. +3
    const int ty = tid >> 4;   // m-group: rows ty*4 .. +3 (packed in pairs)

    unsigned long long acc[2][4];
#pragma unroll
    for (int p = 0; p < 2; ++p)
#pragma unroll
        for (int n = 0; n < 4; ++n) acc[p][n] = 0ull;

    const int KT = K >> 4;
    for (int kt = 0; kt < KT; ++kt) {
        float4 an, bn;
        if (kt + 1 < KT) {
            int k0 = (kt + 1) << 4;
            an = *(const float4*)(rowp[lm] + k0 + lk);
            bn = *(const float4*)(W + (size_t)(ncol0 + lm) * K + k0 + lk);
        }
#pragma unroll
        for (int kk = 0; kk < 16; ++kk) {
            ulonglong2 av = *(const ulonglong2*)&As[kk][ty << 2]; // rows m..m+3, packed
            float4     bv = *(const float4*)&Bs[kk][tx << 2];
            unsigned long long b0 = pack2(bv.x, bv.x);
            unsigned long long b1 = pack2(bv.y, bv.y);
            unsigned long long b2 = pack2(bv.z, bv.z);
            unsigned long long b3 = pack2(bv.w, bv.w);
            acc[0][0] = fma2(av.x, b0, acc[0][0]);
            acc[0][1] = fma2(av.x, b1, acc[0][1]);
            acc[0][2] = fma2(av.x, b2, acc[0][2]);
            acc[0][3] = fma2(av.x, b3, acc[0][3]);
            acc[1][0] = fma2(av.y, b0, acc[1][0]);
            acc[1][1] = fma2(av.y, b1, acc[1][1]);
            acc[1][2] = fma2(av.y, b2, acc[1][2]);
            acc[1][3] = fma2(av.y, b3, acc[1][3]);
        }
        __syncthreads();
        if (kt + 1 < KT) {
            As[lk + 0][lm] = an.x; As[lk + 1][lm] = an.y;
            As[lk + 2][lm] = an.z; As[lk + 3][lm] = an.w;
            Bs[lk + 0][lm] = bn.x; Bs[lk + 1][lm] = bn.y;
            Bs[lk + 2][lm] = bn.z; Bs[lk + 3][lm] = bn.w;
            __syncthreads();
        }
    }

    // write out: rows m0..m0+3, cols n0..n0+3  (+bias)
    const int m0 = ty << 2;
    const int n0 = ncol0 + (tx << 2);
    float4 bsv = *(const float4*)(bias + n0);
#pragma unroll
    for (int p = 0; p < 2; ++p) {
        float2 c0 = unpack2(acc[p][0]);
        float2 c1 = unpack2(acc[p][1]);
        float2 c2 = unpack2(acc[p][2]);
        float2 c3 = unpack2(acc[p][3]);
        int r0 = m0 + 2 * p;
        float4 w0 = make_float4(c0.x + bsv.x, c1.x + bsv.y, c2.x + bsv.z, c3.x + bsv.w);
        float4 w1 = make_float4(c0.y + bsv.x, c1.y + bsv.y, c2.y + bsv.z, c3.y + bsv.w);
        *(float4*)(C + (size_t)r0 * ldc + n0)       = w0;
        *(float4*)(C + (size_t)(r0 + 1) * ldc + n0) = w1;
    }
}

// ---------------- GRU elementwise update + slot reset ------------------------
__global__ void hnew_kernel() {
    int i = blockIdx.x * blockDim.x + threadIdx.x;   // [0, B*H)
    int b = i / HH, u = i % HH;
    const float* gi = g_gi + (size_t)b * G3;
    const float* gh = g_gh + (size_t)b * G3;
    float ir = gi[u], iz = gi[HH + u], in_ = gi[2 * HH + u];
    float hr = gh[u], hz = gh[HH + u], hn  = gh[2 * HH + u];
    float r = 1.0f / (1.0f + expf(-(ir + hr)));
    float z = 1.0f / (1.0f + expf(-(iz + hz)));
    float n = tanhf(in_ + r * hn);
    float h = g_h[i];
    g_h[i] = (1.0f - z) * n + z * h;
    if (i < BB) g_slots[i] = 0ull;   // reset argmax slots for this step's sampling
}

// ---------------- Gumbel-max categorical sampling ----------------------------
// Partitionable threefry: element e = b*V + v of the (B, V) gumbel array draws
// bits = o0 ^ o1 of threefry(key_t, hi=0, lo=e).
__global__ __launch_bounds__(256) void sample_kernel(
    const float* __restrict__ logits, unsigned k0, unsigned k1) {
    __shared__ unsigned long long red[256];
    const int b   = blockIdx.y;            // 0..63
    const int v0  = blockIdx.x * 2000;     // 16 chunks * 2000 = 32000
    const int tid = threadIdx.x;

    unsigned long long best = 0ull;
    for (int i = tid; i < 2000; i += 256) {
        int v = v0 + i;
        unsigned e = (unsigned)(b * VV + v);
        float val = logits[(size_t)b * VV + v] + gumbel_from_bits(jax_bits32(k0, k1, e));
        unsigned long long p =
            ((unsigned long long)orderf(val) << 32) | (0xFFFFFFFFu - (unsigned)v);
        if (p > best) best = p;
    }
    red[tid] = best;
    __syncthreads();
#pragma unroll
    for (int s = 128; s > 0; s >>= 1) {
        if (tid < s) {
            if (red[tid + s] > red[tid]) red[tid] = red[tid + s];
        }
        __syncthreads();
    }
    if (tid == 0) atomicMax(&g_slots[b], red[0]);
}

// ---------------- record sampled ids (B, T) layout, as float -----------------
__global__ void record_kernel(float* __restrict__ ids_out, int t) {
    int b = threadIdx.x;
    if (b < BB) ids_out[(size_t)b * TT + t] = (float)decode_sid(g_slots[b]);
}

// ---------------- launch -----------------------------------------------------
extern "C" void kernel_launch(void* const* d_in, const int* in_sizes, int n_in,
                              void* d_out, int out_size) {
    (void)in_sizes;
    int o = (n_in >= 11) ? 1 : 0;   // optional max_length scalar at slot 1
    const int*   inputs      = (const int*)  d_in[0];
    const float* init_hidden = (const float*)d_in[1 + o];
    const float* att         = (const float*)d_in[2 + o];
    const float* emb         = (const float*)d_in[3 + o];
    const float* W_ih        = (const float*)d_in[4 + o];
    const float* W_hh        = (const float*)d_in[5 + o];
    const float* b_ih        = (const float*)d_in[6 + o];
    const float* b_hh        = (const float*)d_in[7 + o];
    const float* W_out       = (const float*)d_in[8 + o];
    const float* b_out       = (const float*)d_in[9 + o];
    float* out = (float*)d_out;

    const long long TBV = (long long)TT * BB * VV;
    const bool has_ids  = ((long long)out_size >= TBV + (long long)BB * TT);
    float* ids_out = out + TBV;

    // per-step PRNG keys: partitionable (fold-like) split of key(42):
    // keys[t] = threefry2x32(key=(0,42), x0=hi(t)=0, x1=t) -> (o0, o1)
    unsigned keys[TT][2];
    for (int t = 0; t < TT; ++t) {
        unsigned a, b;
        tf2x32(0u, 42u, 0u, (unsigned)t, &a, &b);
        keys[t][0] = a; keys[t][1] = b;
    }

    init_kernel<<<(BB * HH) / 256, 256>>>(init_hidden, att);
    for (int t = 0; t < TT; ++t) {
        // gates: gi (48 blocks) + gh (48 blocks)
        sgemm_step<<<96, 256>>>(emb, inputs, W_ih, W_hh, b_ih, b_hh,
                                W_out, b_out, out, t, 0);
        // GRU update + slot reset
        hnew_kernel<<<(BB * HH) / 256, 256>>>();
        // logits: 500 blocks of 64x64
        sgemm_step<<<500, 256>>>(emb, inputs, W_ih, W_hh, b_ih, b_hh,
                                 W_out, b_out, out + (size_t)t * BB * VV, t, 1);
        // gumbel-max sampling
        sample_kernel<<<dim3(16, 64), 256>>>(out + (size_t)t * BB * VV,
                                             keys[t][0], keys[t][1]);
        if (has_ids) record_kernel<<<1, 64>>>(ids_out, t);
    }
}